// round 15
// baseline (speedup 1.0000x reference)
#include <cuda_runtime.h>
#include <cuda_fp16.h>
#include <cstdint>

// ---------------------------------------------------------------------------
// Grouped MoE MLP, fp16 HMMA (m16n8k16, fp32 accum), fp16 smem + ldmatrix,
// 2 CTAs/SM. R13 + cross-slice fragment double-buffering: while slice s's
// MMAs run, slice s+1's 6 ldmatrix ops stream into the other register
// buffer, hiding LDS latency for 3 of the 4 slices per k-tile.
//
//   pre:   xh = f16(x), w1h = f16(W1), w2h = f16(W2)
//   GEMM1: h  = swiglu(xh @ w1h^T + b1)  -> fp16 [N, H]
//   GEMM2: out= h @ w2h^T + b2           -> fp32 [N, D]
//
// CTA tile 128x128, BK=64 halves, 256 threads (8 warps, 2x4), warp tile
// 64x32, 3-stage cp.async pipeline, XOR-16B-chunk swizzle.
// ---------------------------------------------------------------------------

#define BM 128
#define BN 128
#define BKH 64                              // halves per k-tile (128 bytes)
#define STAGES 3
#define ABYTES   (BM * 128)                 // 16384
#define STAGE_BYTES ((BM + BN) * 128)       // 32768
#define SMEM_BYTES (STAGES * STAGE_BYTES + BN * 4)   // 98816

#define ALPHA_SWIGLU 1.702f
#define LIMIT_SWIGLU 7.0f

// fp16 copies of inputs + intermediate h
__device__ __half g_xh [16384ull * 2880ull];
__device__ __half g_w1h[8ull * 5760ull * 2880ull];
__device__ __half g_w2h[8ull * 2880ull * 2880ull];
__device__ __half g_h  [16384ull * 2880ull];

// ----------------------------- PTX helpers ---------------------------------

__device__ __forceinline__ void cp_async16(uint32_t saddr, const void* gptr, int src_bytes) {
    asm volatile("cp.async.cg.shared.global [%0], [%1], 16, %2;\n"
                 :: "r"(saddr), "l"(gptr), "r"(src_bytes));
}
__device__ __forceinline__ void cp_commit() {
    asm volatile("cp.async.commit_group;\n" ::);
}
template <int Npend>
__device__ __forceinline__ void cp_wait() {
    asm volatile("cp.async.wait_group %0;\n" :: "n"(Npend));
}
__device__ __forceinline__ void ldm_x4(uint32_t* r, uint32_t addr) {
    asm volatile("ldmatrix.sync.aligned.m8n8.x4.shared.b16 {%0,%1,%2,%3}, [%4];"
                 : "=r"(r[0]), "=r"(r[1]), "=r"(r[2]), "=r"(r[3]) : "r"(addr));
}
__device__ __forceinline__ void mma_f16(float* c, const uint32_t* a, const uint32_t* b) {
    asm volatile(
        "mma.sync.aligned.m16n8k16.row.col.f32.f16.f16.f32 "
        "{%0,%1,%2,%3}, {%4,%5,%6,%7}, {%8,%9}, {%0,%1,%2,%3};\n"
        : "+f"(c[0]), "+f"(c[1]), "+f"(c[2]), "+f"(c[3])
        : "r"(a[0]), "r"(a[1]), "r"(a[2]), "r"(a[3]), "r"(b[0]), "r"(b[1]));
}
__device__ __forceinline__ float swiglu_pair(float glu_in, float lin_in) {
    float g = fminf(glu_in, LIMIT_SWIGLU);
    float l = fminf(fmaxf(lin_in, -LIMIT_SWIGLU), LIMIT_SWIGLU);
    float sig = 1.0f / (1.0f + __expf(-ALPHA_SWIGLU * g));
    return g * sig * (l + 1.0f);
}

// ------------------------ f32 -> f16 conversion ----------------------------

__global__ void cvt_f32_f16(const float4* __restrict__ in, __half2* __restrict__ out,
                            size_t n4) {
    size_t i      = (size_t)blockIdx.x * blockDim.x + threadIdx.x;
    size_t stride = (size_t)gridDim.x * blockDim.x;
    for (; i < n4; i += stride) {
        float4 v = in[i];
        out[2 * i]     = __floats2half2_rn(v.x, v.y);
        out[2 * i + 1] = __floats2half2_rn(v.z, v.w);
    }
}

// ---------------------------------------------------------------------------
// EPI=0: GEMM1 epilogue -> h[token, col/2] = f16(swiglu(c0+b0, c1+b1))
// EPI=1: GEMM2 epilogue -> out[token, col] = f32(c + bias)
// ---------------------------------------------------------------------------
template <int EPI>
__global__ void __launch_bounds__(256, 2)
grouped_gemm_ldm(const __half* __restrict__ A,
                 const __half* __restrict__ Bw,
                 const float*  __restrict__ bias,
                 const int*    __restrict__ ntpe,
                 void*         __restrict__ CoutV,
                 int K, int Ncols, int E, int mtiles_per_e, int Ntok) {
    // ---- expert / m-tile resolution ----
    int y  = blockIdx.y;
    int e  = y / mtiles_per_e;
    int mt = y - e * mtiles_per_e;

    int row0 = 0;
    #pragma unroll 1
    for (int i = 0; i < e; i++) row0 += ntpe[i];
    if (row0 >= Ntok) return;
    int rows = ntpe[e];
    if (rows > Ntok - row0) rows = Ntok - row0;
    if (mt * BM >= rows) return;
    int mrows = rows - mt * BM;
    if (mrows > BM) mrows = BM;
    int row_start = row0 + mt * BM;
    int nbase     = blockIdx.x * BN;

    const __half* gA = A  + (size_t)row_start * K;
    const __half* gB = Bw + (size_t)e * Ncols * K + (size_t)nbase * K;

    extern __shared__ __align__(16) char smem[];
    uint32_t smem_base = (uint32_t)__cvta_generic_to_shared(smem);
    float* bias_s = (float*)(smem + STAGES * STAGE_BYTES);

    int tid = threadIdx.x;
    for (int i = tid; i < BN; i += 256) {
        int c = nbase + i;
        bias_s[i] = (c < Ncols) ? bias[(size_t)e * Ncols + c] : 0.0f;
    }

    int KT = K / BKH;   // 45

    // per-stage fill: (BM+BN)*8 = 2048 x 16B chunks, 8 per thread
    auto fill = [&](int kt) {
        uint32_t sbase = smem_base + (kt % STAGES) * STAGE_BYTES;
        const __half* gAk = gA + kt * BKH;
        const __half* gBk = gB + kt * BKH;
        #pragma unroll
        for (int l = 0; l < 8; l++) {
            int c = tid + 256 * l;
            if (c < BM * 8) {                       // A: 128 rows x 8 chunks
                int r  = c >> 3;
                int ch = c & 7;
                uint32_t dst = sbase + r * 128 + ((ch ^ (r & 7)) << 4);
                bool v = (r < mrows);
                cp_async16(dst, gAk + (size_t)(v ? r : 0) * K + ch * 8, v ? 16 : 0);
            } else {                                // B: 128 rows x 8 chunks
                int c2 = c - BM * 8;
                int n  = c2 >> 3;
                int ch = c2 & 7;
                uint32_t dst = sbase + ABYTES + n * 128 + ((ch ^ (n & 7)) << 4);
                bool v = (nbase + n < Ncols);
                cp_async16(dst, gBk + (size_t)(v ? n : 0) * K + ch * 8, v ? 16 : 0);
            }
        }
        cp_commit();
    };

    // warp layout: 2 (M) x 4 (N); warp tile 64x32; 4x4 m16n8 mma tiles
    int wid  = tid >> 5;
    int lane = tid & 31;
    int wm   = wid & 1;
    int wn   = wid >> 1;
    int grp  = lane >> 2;        // 0..7
    int tig  = lane & 3;         // 0..3

    // ldmatrix per-lane source coords; row bases are multiples of 16 so the
    // swizzle key reduces to lane&7 (constant per thread)
    int xkey  = lane & 7;
    int a_row = (lane & 7) + (lane & 8);          // 0..15 within m16 tile
    int abit  = lane >> 4;
    int b_row = (lane & 7) + ((lane & 16) >> 1);  // 0..15 within n16 pair
    int bbit  = (lane >> 3) & 1;

    // base offsets; per-i / per-jp strides are compile-time immediates (i*2048)
    uint32_t arow0 = (uint32_t)((wm * 64 + a_row) * 128);
    uint32_t brow0 = (uint32_t)(ABYTES + (wn * 32 + b_row) * 128);

    float acc[4][4][4];
    #pragma unroll
    for (int i = 0; i < 4; i++)
        #pragma unroll
        for (int j = 0; j < 4; j++)
            #pragma unroll
            for (int r = 0; r < 4; r++) acc[i][j][r] = 0.0f;

    fill(0);
    if (KT > 1) fill(1);

    // double-buffered fragments (indexed by slice parity)
    uint32_t afr[2][4][4];
    uint32_t bfr[2][2][4];

    for (int kt = 0; kt < KT; kt++) {
        cp_wait<1>();            // stage kt resident (this thread's groups)
        __syncthreads();         // all warps done with stage kt-1, fills visible

        if (kt + 2 < KT) fill(kt + 2);      // overwrites stage (kt-1)%3 — safe
        else             cp_commit();

        uint32_t sbase = smem_base + (kt % STAGES) * STAGE_BYTES;

        // preload slice 0 fragments into buffer 0
        {
            uint32_t at = ((uint32_t)((abit) ^ xkey)) << 4;
            uint32_t bt = ((uint32_t)((bbit) ^ xkey)) << 4;
            #pragma unroll
            for (int i = 0; i < 4; i++)
                ldm_x4(afr[0][i], sbase + arow0 + i * 2048 + at);
            #pragma unroll
            for (int jp = 0; jp < 2; jp++)
                ldm_x4(bfr[0][jp], sbase + brow0 + jp * 2048 + bt);
        }

        #pragma unroll
        for (int s = 0; s < 4; s++) {       // 4 x k16 slices per k-tile
            int cb = s & 1;
            if (s < 3) {
                // prefetch slice s+1 into the other buffer while MMAs run
                int nb = (s + 1) & 1;
                uint32_t at = ((uint32_t)((2 * (s + 1) + abit) ^ xkey)) << 4;
                uint32_t bt = ((uint32_t)((2 * (s + 1) + bbit) ^ xkey)) << 4;
                #pragma unroll
                for (int i = 0; i < 4; i++)
                    ldm_x4(afr[nb][i], sbase + arow0 + i * 2048 + at);
                #pragma unroll
                for (int jp = 0; jp < 2; jp++)
                    ldm_x4(bfr[nb][jp], sbase + brow0 + jp * 2048 + bt);
            }
            #pragma unroll
            for (int i = 0; i < 4; i++)
                #pragma unroll
                for (int j = 0; j < 4; j++)
                    mma_f16(acc[i][j], afr[cb][i], &bfr[cb][j >> 1][(j & 1) * 2]);
        }
    }

    // ---- epilogue ----
    if (EPI == 0) {
        __half* Cout = (__half*)CoutV;
        int Hout = Ncols >> 1;
        #pragma unroll
        for (int j = 0; j < 4; j++) {
            int lc  = wn * 32 + j * 8 + tig * 2;       // local even col
            float b0 = bias_s[lc], b1 = bias_s[lc + 1];
            int hc = (nbase + lc) >> 1;
            #pragma unroll
            for (int i = 0; i < 4; i++) {
                int m0 = wm * 64 + i * 16 + grp;
                if (m0 < mrows)
                    Cout[(size_t)(row_start + m0) * Hout + hc] =
                        __float2half(swiglu_pair(acc[i][j][0] + b0, acc[i][j][1] + b1));
                if (m0 + 8 < mrows)
                    Cout[(size_t)(row_start + m0 + 8) * Hout + hc] =
                        __float2half(swiglu_pair(acc[i][j][2] + b0, acc[i][j][3] + b1));
            }
        }
    } else {
        float* Cout = (float*)CoutV;
        #pragma unroll
        for (int j = 0; j < 4; j++) {
            int lc  = wn * 32 + j * 8 + tig * 2;
            int col = nbase + lc;
            if (col < Ncols) {
                float b0 = bias_s[lc], b1 = bias_s[lc + 1];
                #pragma unroll
                for (int i = 0; i < 4; i++) {
                    int m0 = wm * 64 + i * 16 + grp;
                    if (m0 < mrows) {
                        float2 v = make_float2(acc[i][j][0] + b0, acc[i][j][1] + b1);
                        *(float2*)(Cout + (size_t)(row_start + m0) * Ncols + col) = v;
                    }
                    if (m0 + 8 < mrows) {
                        float2 v = make_float2(acc[i][j][2] + b0, acc[i][j][3] + b1);
                        *(float2*)(Cout + (size_t)(row_start + m0 + 8) * Ncols + col) = v;
                    }
                }
            }
        }
    }
}

// Zero padding rows (tokens >= sum(ntpe)); no-op for the equal-split inputs.
__global__ void zero_tail_kernel(float* __restrict__ out, const int* __restrict__ ntpe,
                                 int E, int Ntok, int D) {
    int total = 0;
    for (int i = 0; i < E; i++) total += ntpe[i];
    if (total >= Ntok) return;
    size_t nelem  = (size_t)(Ntok - total) * D;
    float* base   = out + (size_t)total * D;
    size_t idx    = (size_t)blockIdx.x * blockDim.x + threadIdx.x;
    size_t stride = (size_t)gridDim.x * blockDim.x;
    for (; idx < nelem; idx += stride) base[idx] = 0.0f;
}

// ---------------------------------------------------------------------------

extern "C" void kernel_launch(void* const* d_in, const int* in_sizes, int n_in,
                              void* d_out, int out_size) {
    const float* x   = (const float*)d_in[0];
    const float* w1  = (const float*)d_in[1];
    const float* b1  = (const float*)d_in[2];
    const float* w2  = (const float*)d_in[3];
    const float* b2  = (const float*)d_in[4];
    const int*   ntp = (const int*)  d_in[5];

    int E  = in_sizes[5];                 // 8
    int D  = in_sizes[4] / E;             // 2880
    int H2 = in_sizes[2] / E;             // 5760
    int H  = H2 / 2;                      // 2880
    int N  = in_sizes[0] / D;             // 16384

    __half *xh, *w1h, *w2h, *hh;
    cudaGetSymbolAddress((void**)&xh,  g_xh);
    cudaGetSymbolAddress((void**)&w1h, g_w1h);
    cudaGetSymbolAddress((void**)&w2h, g_w2h);
    cudaGetSymbolAddress((void**)&hh,  g_h);

    // one-time f32 -> f16 conversions (DRAM-bound; serial is optimal)
    {
        size_t nx  = (size_t)in_sizes[0] / 4;
        size_t nw1 = (size_t)in_sizes[1] / 4;
        size_t nw2 = (size_t)in_sizes[3] / 4;
        cvt_f32_f16<<<2368, 256>>>((const float4*)x,  (__half2*)xh,  nx);
        cvt_f32_f16<<<2368, 256>>>((const float4*)w1, (__half2*)w1h, nw1);
        cvt_f32_f16<<<2368, 256>>>((const float4*)w2, (__half2*)w2h, nw2);
    }

    cudaFuncSetAttribute((const void*)grouped_gemm_ldm<0>,
                         cudaFuncAttributeMaxDynamicSharedMemorySize, SMEM_BYTES);
    cudaFuncSetAttribute((const void*)grouped_gemm_ldm<1>,
                         cudaFuncAttributeMaxDynamicSharedMemorySize, SMEM_BYTES);

    int mtiles_per_e = (N + BM - 1) / BM;             // 128

    // GEMM1 + bias + swiglu -> g_h [N, H] f16
    dim3 g1((H2 + BN - 1) / BN, E * mtiles_per_e);    // (45, 1024)
    grouped_gemm_ldm<0><<<g1, 256, SMEM_BYTES>>>(xh, w1h, b1, ntp, hh,
                                                 /*K=*/D, /*Ncols=*/H2, E, mtiles_per_e, N);

    // GEMM2 + bias -> out [N, D] f32
    dim3 g2((D + BN - 1) / BN, E * mtiles_per_e);     // (23, 1024)
    grouped_gemm_ldm<1><<<g2, 256, SMEM_BYTES>>>(hh, w2h, b2, ntp, d_out,
                                                 /*K=*/H, /*Ncols=*/D, E, mtiles_per_e, N);

    // zero padding rows (no-op for equal split)
    zero_tail_kernel<<<256, 256>>>((float*)d_out, ntp, E, N, D);
}

// round 16
// speedup vs baseline: 1.0114x; 1.0114x over previous
#include <cuda_runtime.h>
#include <cuda_fp16.h>
#include <cstdint>

// ---------------------------------------------------------------------------
// Grouped MoE MLP, fp16 HMMA (m16n8k16, fp32 accum), fp16 smem + ldmatrix,
// 2 CTAs/SM, CTA tile 128x160, warp tile 64x40 (wider: fewer fragment bytes
// per MMA -> relieves the co-bound smem crossbar), 3-stage cp.async pipeline.
//
//   pre:   xh = f16(x), w1h = f16(W1), w2h = f16(W2)
//   GEMM1: h  = swiglu(xh @ w1h^T + b1)  -> fp16 [N, H]
//   GEMM2: out= h @ w2h^T + b2           -> fp32 [N, D]
//
// 256 threads (8 warps, 2x4). Per k16 slice each warp: 4x A ldm.x4 +
// 2x B ldm.x4 + 1x B ldm.x2 -> 20 MMAs. XOR-16B-chunk swizzle keeps all
// cp.async stores and ldmatrix reads bank-conflict-free.
// ---------------------------------------------------------------------------

#define BM 128
#define BN 160
#define BKH 64                              // halves per k-tile (128 bytes)
#define STAGES 3
#define ABYTES   (BM * 128)                 // 16384
#define STAGE_BYTES ((BM + BN) * 128)       // 36864
#define SMEM_BYTES (STAGES * STAGE_BYTES + BN * 4)   // 111232

#define ALPHA_SWIGLU 1.702f
#define LIMIT_SWIGLU 7.0f

// fp16 copies of inputs + intermediate h
__device__ __half g_xh [16384ull * 2880ull];
__device__ __half g_w1h[8ull * 5760ull * 2880ull];
__device__ __half g_w2h[8ull * 2880ull * 2880ull];
__device__ __half g_h  [16384ull * 2880ull];

// ----------------------------- PTX helpers ---------------------------------

__device__ __forceinline__ void cp_async16(uint32_t saddr, const void* gptr, int src_bytes) {
    asm volatile("cp.async.cg.shared.global [%0], [%1], 16, %2;\n"
                 :: "r"(saddr), "l"(gptr), "r"(src_bytes));
}
__device__ __forceinline__ void cp_commit() {
    asm volatile("cp.async.commit_group;\n" ::);
}
template <int Npend>
__device__ __forceinline__ void cp_wait() {
    asm volatile("cp.async.wait_group %0;\n" :: "n"(Npend));
}
__device__ __forceinline__ void ldm_x4(uint32_t* r, uint32_t addr) {
    asm volatile("ldmatrix.sync.aligned.m8n8.x4.shared.b16 {%0,%1,%2,%3}, [%4];"
                 : "=r"(r[0]), "=r"(r[1]), "=r"(r[2]), "=r"(r[3]) : "r"(addr));
}
__device__ __forceinline__ void ldm_x2(uint32_t* r, uint32_t addr) {
    asm volatile("ldmatrix.sync.aligned.m8n8.x2.shared.b16 {%0,%1}, [%2];"
                 : "=r"(r[0]), "=r"(r[1]) : "r"(addr));
}
__device__ __forceinline__ void mma_f16(float* c, const uint32_t* a, const uint32_t* b) {
    asm volatile(
        "mma.sync.aligned.m16n8k16.row.col.f32.f16.f16.f32 "
        "{%0,%1,%2,%3}, {%4,%5,%6,%7}, {%8,%9}, {%0,%1,%2,%3};\n"
        : "+f"(c[0]), "+f"(c[1]), "+f"(c[2]), "+f"(c[3])
        : "r"(a[0]), "r"(a[1]), "r"(a[2]), "r"(a[3]), "r"(b[0]), "r"(b[1]));
}
__device__ __forceinline__ float swiglu_pair(float glu_in, float lin_in) {
    float g = fminf(glu_in, LIMIT_SWIGLU);
    float l = fminf(fmaxf(lin_in, -LIMIT_SWIGLU), LIMIT_SWIGLU);
    float sig = 1.0f / (1.0f + __expf(-ALPHA_SWIGLU * g));
    return g * sig * (l + 1.0f);
}

// ------------------------ f32 -> f16 conversion ----------------------------

__global__ void cvt_f32_f16(const float4* __restrict__ in, __half2* __restrict__ out,
                            size_t n4) {
    size_t i      = (size_t)blockIdx.x * blockDim.x + threadIdx.x;
    size_t stride = (size_t)gridDim.x * blockDim.x;
    for (; i < n4; i += stride) {
        float4 v = in[i];
        out[2 * i]     = __floats2half2_rn(v.x, v.y);
        out[2 * i + 1] = __floats2half2_rn(v.z, v.w);
    }
}

// ---------------------------------------------------------------------------
// EPI=0: GEMM1 epilogue -> h[token, col/2] = f16(swiglu(c0+b0, c1+b1))
// EPI=1: GEMM2 epilogue -> out[token, col] = f32(c + bias)
// ---------------------------------------------------------------------------
template <int EPI>
__global__ void __launch_bounds__(256, 2)
grouped_gemm_ldm(const __half* __restrict__ A,
                 const __half* __restrict__ Bw,
                 const float*  __restrict__ bias,
                 const int*    __restrict__ ntpe,
                 void*         __restrict__ CoutV,
                 int K, int Ncols, int E, int mtiles_per_e, int Ntok) {
    // ---- expert / m-tile resolution ----
    int y  = blockIdx.y;
    int e  = y / mtiles_per_e;
    int mt = y - e * mtiles_per_e;

    int row0 = 0;
    #pragma unroll 1
    for (int i = 0; i < e; i++) row0 += ntpe[i];
    if (row0 >= Ntok) return;
    int rows = ntpe[e];
    if (rows > Ntok - row0) rows = Ntok - row0;
    if (mt * BM >= rows) return;
    int mrows = rows - mt * BM;
    if (mrows > BM) mrows = BM;
    int row_start = row0 + mt * BM;
    int nbase     = blockIdx.x * BN;

    const __half* gA = A  + (size_t)row_start * K;
    const __half* gB = Bw + (size_t)e * Ncols * K + (size_t)nbase * K;

    extern __shared__ __align__(16) char smem[];
    uint32_t smem_base = (uint32_t)__cvta_generic_to_shared(smem);
    float* bias_s = (float*)(smem + STAGES * STAGE_BYTES);

    int tid = threadIdx.x;
    for (int i = tid; i < BN; i += 256) {
        int c = nbase + i;
        bias_s[i] = (c < Ncols) ? bias[(size_t)e * Ncols + c] : 0.0f;
    }

    int KT = K / BKH;   // 45

    // per-stage fill: (BM+BN)*8 = 2304 x 16B chunks, 9 per thread
    auto fill = [&](int kt) {
        uint32_t sbase = smem_base + (kt % STAGES) * STAGE_BYTES;
        const __half* gAk = gA + kt * BKH;
        const __half* gBk = gB + kt * BKH;
        #pragma unroll
        for (int l = 0; l < 9; l++) {
            int c = tid + 256 * l;
            if (c < BM * 8) {                       // A: 128 rows x 8 chunks
                int r  = c >> 3;
                int ch = c & 7;
                uint32_t dst = sbase + r * 128 + ((ch ^ (r & 7)) << 4);
                bool v = (r < mrows);
                cp_async16(dst, gAk + (size_t)(v ? r : 0) * K + ch * 8, v ? 16 : 0);
            } else {                                // B: 160 rows x 8 chunks
                int c2 = c - BM * 8;
                int n  = c2 >> 3;
                int ch = c2 & 7;
                uint32_t dst = sbase + ABYTES + n * 128 + ((ch ^ (n & 7)) << 4);
                bool v = (nbase + n < Ncols);
                cp_async16(dst, gBk + (size_t)(v ? n : 0) * K + ch * 8, v ? 16 : 0);
            }
        }
        cp_commit();
    };

    // warp layout: 2 (M) x 4 (N); warp tile 64x40; 4x5 m16n8 mma tiles
    int wid  = tid >> 5;
    int lane = tid & 31;
    int wm   = wid & 1;
    int wn   = wid >> 1;
    int grp  = lane >> 2;        // 0..7
    int tig  = lane & 3;         // 0..3

    // ldmatrix per-lane source coords; all row bases are multiples of 8 so
    // the swizzle key reduces to lane&7 (constant per thread)
    int xkey  = lane & 7;
    int a_row = (lane & 7) + (lane & 8);          // 0..15 within m16 tile
    int abit  = lane >> 4;
    int b_row = (lane & 7) + ((lane & 16) >> 1);  // 0..15 within n16 pair
    int bbit  = (lane >> 3) & 1;
    int b2row = lane & 7;                          // x2: lanes 0..15 matter
    int b2bit = (lane >> 3) & 1;

    uint32_t arow0 = (uint32_t)((wm * 64 + a_row) * 128);
    uint32_t brow_p0 = (uint32_t)(ABYTES + (wn * 40 + b_row) * 128);           // n16 pair 0
    uint32_t brow_p1 = (uint32_t)(ABYTES + (wn * 40 + 16 + b_row) * 128);      // n16 pair 1
    uint32_t brow_x2 = (uint32_t)(ABYTES + (wn * 40 + 32 + b2row) * 128);      // last n8

    float acc[4][5][4];
    #pragma unroll
    for (int i = 0; i < 4; i++)
        #pragma unroll
        for (int j = 0; j < 5; j++)
            #pragma unroll
            for (int r = 0; r < 4; r++) acc[i][j][r] = 0.0f;

    fill(0);
    if (KT > 1) fill(1);

    for (int kt = 0; kt < KT; kt++) {
        cp_wait<1>();            // stage kt resident (this thread's groups)
        __syncthreads();         // all warps done with stage kt-1, fills visible

        if (kt + 2 < KT) fill(kt + 2);      // overwrites stage (kt-1)%3 — safe
        else             cp_commit();

        uint32_t sbase = smem_base + (kt % STAGES) * STAGE_BYTES;

        #pragma unroll
        for (int s = 0; s < 4; s++) {       // 4 x k16 slices per k-tile
            uint32_t aterm  = ((uint32_t)((2 * s + abit) ^ xkey)) << 4;
            uint32_t bterm  = ((uint32_t)((2 * s + bbit) ^ xkey)) << 4;
            uint32_t b2term = ((uint32_t)((2 * s + b2bit) ^ xkey)) << 4;
            // batch all fragment loads (latencies overlap), then the MMAs
            uint32_t afr[4][4];
            uint32_t bfr[2][4];
            uint32_t bf2[2];
            #pragma unroll
            for (int i = 0; i < 4; i++)
                ldm_x4(afr[i], sbase + arow0 + i * 2048 + aterm);
            ldm_x4(bfr[0], sbase + brow_p0 + bterm);
            ldm_x4(bfr[1], sbase + brow_p1 + bterm);
            ldm_x2(bf2,    sbase + brow_x2 + b2term);
            #pragma unroll
            for (int i = 0; i < 4; i++) {
                #pragma unroll
                for (int j = 0; j < 4; j++)
                    mma_f16(acc[i][j], afr[i], &bfr[j >> 1][(j & 1) * 2]);
                mma_f16(acc[i][4], afr[i], bf2);
            }
        }
    }

    // ---- epilogue ----
    if (EPI == 0) {
        __half* Cout = (__half*)CoutV;
        int Hout = Ncols >> 1;
        #pragma unroll
        for (int j = 0; j < 5; j++) {
            int lc  = wn * 40 + j * 8 + tig * 2;       // local even col
            float b0 = bias_s[lc], b1 = bias_s[lc + 1];
            int hc = (nbase + lc) >> 1;
            #pragma unroll
            for (int i = 0; i < 4; i++) {
                int m0 = wm * 64 + i * 16 + grp;
                if (m0 < mrows)
                    Cout[(size_t)(row_start + m0) * Hout + hc] =
                        __float2half(swiglu_pair(acc[i][j][0] + b0, acc[i][j][1] + b1));
                if (m0 + 8 < mrows)
                    Cout[(size_t)(row_start + m0 + 8) * Hout + hc] =
                        __float2half(swiglu_pair(acc[i][j][2] + b0, acc[i][j][3] + b1));
            }
        }
    } else {
        float* Cout = (float*)CoutV;
        #pragma unroll
        for (int j = 0; j < 5; j++) {
            int lc  = wn * 40 + j * 8 + tig * 2;
            int col = nbase + lc;
            if (col < Ncols) {
                float b0 = bias_s[lc], b1 = bias_s[lc + 1];
                #pragma unroll
                for (int i = 0; i < 4; i++) {
                    int m0 = wm * 64 + i * 16 + grp;
                    if (m0 < mrows) {
                        float2 v = make_float2(acc[i][j][0] + b0, acc[i][j][1] + b1);
                        *(float2*)(Cout + (size_t)(row_start + m0) * Ncols + col) = v;
                    }
                    if (m0 + 8 < mrows) {
                        float2 v = make_float2(acc[i][j][2] + b0, acc[i][j][3] + b1);
                        *(float2*)(Cout + (size_t)(row_start + m0 + 8) * Ncols + col) = v;
                    }
                }
            }
        }
    }
}

// Zero padding rows (tokens >= sum(ntpe)); no-op for the equal-split inputs.
__global__ void zero_tail_kernel(float* __restrict__ out, const int* __restrict__ ntpe,
                                 int E, int Ntok, int D) {
    int total = 0;
    for (int i = 0; i < E; i++) total += ntpe[i];
    if (total >= Ntok) return;
    size_t nelem  = (size_t)(Ntok - total) * D;
    float* base   = out + (size_t)total * D;
    size_t idx    = (size_t)blockIdx.x * blockDim.x + threadIdx.x;
    size_t stride = (size_t)gridDim.x * blockDim.x;
    for (; idx < nelem; idx += stride) base[idx] = 0.0f;
}

// ---------------------------------------------------------------------------

extern "C" void kernel_launch(void* const* d_in, const int* in_sizes, int n_in,
                              void* d_out, int out_size) {
    const float* x   = (const float*)d_in[0];
    const float* w1  = (const float*)d_in[1];
    const float* b1  = (const float*)d_in[2];
    const float* w2  = (const float*)d_in[3];
    const float* b2  = (const float*)d_in[4];
    const int*   ntp = (const int*)  d_in[5];

    int E  = in_sizes[5];                 // 8
    int D  = in_sizes[4] / E;             // 2880
    int H2 = in_sizes[2] / E;             // 5760
    int H  = H2 / 2;                      // 2880
    int N  = in_sizes[0] / D;             // 16384

    __half *xh, *w1h, *w2h, *hh;
    cudaGetSymbolAddress((void**)&xh,  g_xh);
    cudaGetSymbolAddress((void**)&w1h, g_w1h);
    cudaGetSymbolAddress((void**)&w2h, g_w2h);
    cudaGetSymbolAddress((void**)&hh,  g_h);

    // one-time f32 -> f16 conversions (DRAM-bound; serial is optimal)
    {
        size_t nx  = (size_t)in_sizes[0] / 4;
        size_t nw1 = (size_t)in_sizes[1] / 4;
        size_t nw2 = (size_t)in_sizes[3] / 4;
        cvt_f32_f16<<<2368, 256>>>((const float4*)x,  (__half2*)xh,  nx);
        cvt_f32_f16<<<2368, 256>>>((const float4*)w1, (__half2*)w1h, nw1);
        cvt_f32_f16<<<2368, 256>>>((const float4*)w2, (__half2*)w2h, nw2);
    }

    cudaFuncSetAttribute((const void*)grouped_gemm_ldm<0>,
                         cudaFuncAttributeMaxDynamicSharedMemorySize, SMEM_BYTES);
    cudaFuncSetAttribute((const void*)grouped_gemm_ldm<1>,
                         cudaFuncAttributeMaxDynamicSharedMemorySize, SMEM_BYTES);

    int mtiles_per_e = (N + BM - 1) / BM;             // 128

    // GEMM1 + bias + swiglu -> g_h [N, H] f16
    dim3 g1((H2 + BN - 1) / BN, E * mtiles_per_e);    // (36, 1024)
    grouped_gemm_ldm<0><<<g1, 256, SMEM_BYTES>>>(xh, w1h, b1, ntp, hh,
                                                 /*K=*/D, /*Ncols=*/H2, E, mtiles_per_e, N);

    // GEMM2 + bias -> out [N, D] f32
    dim3 g2((D + BN - 1) / BN, E * mtiles_per_e);     // (18, 1024)
    grouped_gemm_ldm<1><<<g2, 256, SMEM_BYTES>>>(hh, w2h, b2, ntp, d_out,
                                                 /*K=*/H, /*Ncols=*/D, E, mtiles_per_e, N);

    // zero padding rows (no-op for equal split)
    zero_tail_kernel<<<256, 256>>>((float*)d_out, ntp, E, N, D);
}